// round 15
// baseline (speedup 1.0000x reference)
#include <cuda_runtime.h>
#include <cstdint>
#include <dlfcn.h>

// ============================================================================
// Steerable pyramid, frequency-domain, M=N=512, B=4, C=3, K=4, S=5.
// OUTPUT = float32 REAL PARTS of each tuple element, concatenated (7339008 f32).
//
// 10 launches:
//   1-2  forward FFT2 of x -> g_X          (DIT shuffle-FFT passes)
//   3-4  highpass inverse FFT2 -> out0
//   5    fold_all (all 5 band folds + lowpass fold)
//   6-7  j0 (Q=256) -> out1   8-9  j1 (Q=128) -> out2
//   10   fused_all: ifft2 Q=64/32/16/16 -> out3..6 in ONE launch
//
// DIT shuffle FFT (L = 32*R): n = lane + 32*b  -> COALESCED loads.
//   X[R*k1+k2] = SUM_lane e^{sg 2pi i lane k1/32} [ e^{sg 2pi i lane k2/L}
//                  * FFT_R_regs(f[lane+32b])(k2) ]
//   register FFT_R (DIF, bit-rev k2) -> per-lane twiddle chain ->
//   5-stage shfl_xor FFT32 (bit-rev k1). Staging smem XOR-swizzled
//   (col ^ ((col>>4)&(R-1)) => <=2-way conflicts). CHUNKS loop => 384-block
//   grids = single wave.
// ============================================================================

#define MM 512
#define NIMG 12
#define KANG 4
#define PI_F 3.14159265358979323846f
#define PADR 2
#define FULLM 0xffffffffu

#define X_CAP    ((size_t)NIMG * MM * MM)
#define POOL_CAP ((size_t)11532288)
#define OUT_TOTAL ((size_t)7339008)

__device__ float2 g_X[NIMG * MM * MM];
__device__ float2 g_P[11532288];

#define OFF_FT   ((size_t)0)
#define OFF_W0   ((size_t)3145728)
#define OFF_T0   ((size_t)6291456)
#define OFF_W1   ((size_t)9437184)
#define OFF_T1   ((size_t)10223616)
#define OFF_W2   ((size_t)11010048)
#define OFF_W3   ((size_t)11403264)
#define OFF_W4   ((size_t)11501568)
#define OFF_WL   ((size_t)11526144)

__host__ __device__ constexpr int clog2(int n) { return n <= 1 ? 0 : 1 + clog2(n >> 1); }
__host__ __device__ constexpr int brevc(int x, int bits) {
    int r = 0;
    for (int i = 0; i < bits; i++) r = (r << 1) | ((x >> i) & 1);
    return r;
}

__device__ __forceinline__ float2 cmul(float2 a, float2 b) {
    return make_float2(a.x * b.x - a.y * b.y, a.x * b.y + a.y * b.x);
}

// ============================================================================
// DIT shuffle-FFT 2D pass: rows of [batch][L][L], one warp per row, store
// TRANSPOSED in natural order. CHUNKS row-groups per block.
// ============================================================================
template<int R, int CHUNKS, bool REAL_IN, bool REAL_OUT>
__global__ void sfft_pass_kernel(const float* __restrict__ ext_in, size_t src_cap,
                                 int src_sel, size_t src_off,
                                 float* __restrict__ ext_out, size_t dst_base, size_t dst_cap,
                                 int dst_sel, size_t dst_off,
                                 const float* __restrict__ filt, size_t filt_cap,
                                 int sign, float scale) {
    constexpr int L = 32 * R;
    constexpr int LOG_R = clog2(R);
    constexpr int RPB = 8;
    __shared__ float2 sm[RPB][L + 1];
    __shared__ float2 twR[R];

    const int tid   = threadIdx.x;
    const int lane  = tid & 31;
    const int w     = tid >> 5;
    const int batch = blockIdx.y;
    const float sg  = (sign > 0) ? 1.0f : -1.0f;

    if (tid < R) {
        float s, c;
        sincosf(sg * 2.0f * PI_F * (float)tid / (float)R, &s, &c);
        twR[tid] = make_float2(c, s);
    }
    // per-lane constants
    float2 w32;   // e^{sg 2pi i (lane&15)/32}
    {
        float s, c;
        sincosf(sg * 2.0f * PI_F * (float)(lane & 15) / 32.0f, &s, &c);
        w32 = make_float2(c, s);
    }
    float2 wl;    // e^{sg 2pi i lane / L}
    {
        float s, c;
        sincosf(sg * 2.0f * PI_F * (float)lane / (float)L, &s, &c);
        wl = make_float2(c, s);
    }
    const int b5 = (int)(__brev((unsigned)lane) >> 27);
    __syncthreads();

    for (int ch = 0; ch < CHUNKS; ch++) {
        const int r0 = (blockIdx.x * CHUNKS + ch) * RPB;
        const int r  = r0 + w;
        const size_t rowb = ((size_t)batch * L + r) * L;

        // ---- coalesced load: lane holds f[lane + 32*b]
        float2 v[R];
        if (REAL_IN) {
#pragma unroll
            for (int b = 0; b < R; b++) {
                size_t o = rowb + lane + 32 * b;
                float val = (o < src_cap) ? ext_in[o] : 0.0f;
                v[b] = make_float2(val, 0.0f);
            }
        } else {
            const float2* base = (src_sel == 0 ? g_X : g_P) + src_off;
            if (filt) {
                const size_t frow = (size_t)r * L + lane;
#pragma unroll
                for (int b = 0; b < R; b++) {
                    float2 t = base[rowb + lane + 32 * b];
                    float ff = (frow + 32 * b < filt_cap) ? filt[frow + 32 * b] : 0.0f;
                    v[b] = make_float2(t.x * ff, t.y * ff);
                }
            } else {
#pragma unroll
                for (int b = 0; b < R; b++) v[b] = base[rowb + lane + 32 * b];
            }
        }

        // ---- register FFT_R over b (DIF; reg q holds k2 = brevc(q))
#pragma unroll
        for (int h2 = R / 2; h2 >= 1; h2 >>= 1) {
#pragma unroll
            for (int g = 0; g < R; g += 2 * h2) {
#pragma unroll
                for (int j = 0; j < h2; j++) {
                    float2 lo = v[g + j], hi2 = v[g + j + h2];
                    v[g + j] = make_float2(lo.x + hi2.x, lo.y + hi2.y);
                    float2 d = make_float2(lo.x - hi2.x, lo.y - hi2.y);
                    v[g + j + h2] = cmul(d, twR[j * (R / (2 * h2))]);
                }
            }
        }

        // ---- twiddle: v[q] *= wl^{k2}, k2 = brevc(q)  (chain in k2-order)
        {
            float2 cur = wl;
#pragma unroll
            for (int k2 = 1; k2 < R; k2++) {
                if (k2 > 1) cur = cmul(cur, wl);
                constexpr_fold:;
                const int qq = brevc(k2, LOG_R);
                v[qq] = cmul(v[qq], cur);
            }
        }

        // ---- FFT32 across lanes (5 shfl_xor DIF stages; lane c -> k1=brev5(c))
#pragma unroll
        for (int st = 0; st < 5; st++) {
            const int h = 16 >> st;
            const int t = (lane & (h - 1)) * (16 / h);
            const float wre = __shfl_sync(FULLM, w32.x, t);
            const float wim = __shfl_sync(FULLM, w32.y, t);
            const bool hi = (lane & h) != 0;
#pragma unroll
            for (int b = 0; b < R; b++) {
                float ox = __shfl_xor_sync(FULLM, v[b].x, h);
                float oy = __shfl_xor_sync(FULLM, v[b].y, h);
                if (hi) {
                    float dx = ox - v[b].x, dy = oy - v[b].y;
                    v[b] = make_float2(dx * wre - dy * wim, dx * wim + dy * wre);
                } else {
                    v[b].x += ox; v[b].y += oy;
                }
            }
        }

        // ---- stage to smem, natural order, XOR swizzle
#pragma unroll
        for (int q = 0; q < R; q++) {
            const int col = R * b5 + brevc(q, LOG_R);
            const int ph = col ^ ((col >> 4) & (R - 1));
            sm[w][ph] = v[q];
        }
        __syncthreads();

        // ---- transposed store
        if (REAL_OUT) {
            for (int idx = tid; idx < RPB * L; idx += blockDim.x) {
                int rl = idx & (RPB - 1);
                int cc = idx >> 3;
                int ph = cc ^ ((cc >> 4) & (R - 1));
                size_t o = dst_base + ((size_t)batch * L + cc) * L + (r0 + rl);
                if (o < dst_cap) ext_out[o] = sm[rl][ph].x * scale;
            }
        } else {
            float2* out = (dst_sel == 0 ? g_X : g_P);
            const size_t cap = (dst_sel == 0 ? X_CAP : POOL_CAP);
            for (int idx = tid; idx < RPB * L; idx += blockDim.x) {
                int rl = idx & (RPB - 1);
                int cc = idx >> 3;
                int ph = cc ^ ((cc >> 4) & (R - 1));
                float2 t = sm[rl][ph];
                size_t o = dst_off + ((size_t)batch * L + cc) * L + (r0 + rl);
                if (o < cap) out[o] = make_float2(t.x * scale, t.y * scale);
            }
        }
        __syncthreads();
    }
}

// ============================================================================
// smem warp FFT for the fused small-band kernels
// ============================================================================
template<int L>
__device__ __forceinline__ int digitrev(int p) {
    constexpr int LOG = clog2(L);
    constexpr int NS4 = LOG >> 1;
    int k = 0;
    int shift = LOG;
#pragma unroll
    for (int s = 0; s < NS4; s++) {
        shift -= 2;
        k |= ((p >> shift) & 3) << (2 * s);
    }
    if (LOG & 1) k |= (p & 1) << (2 * NS4);
    return k;
}

template<int L>
__device__ __forceinline__ void warp_fft4(float2* d, const float2* tw, int lane, int sign) {
    constexpr int LOG = clog2(L);
    constexpr int NS4 = LOG >> 1;
    const float s = (sign > 0) ? 1.0f : -1.0f;
#pragma unroll
    for (int st = 0; st < NS4; st++) {
        const int m = L >> (2 + 2 * st);
        const int tws = 1 << (2 * st);
        for (int t = lane; t < (L >> 2); t += 32) {
            const int j = t & (m - 1);
            const int base = ((t & ~(m - 1)) << 2) + j;
            float2 a = d[base], b = d[base + m], c = d[base + 2 * m], e = d[base + 3 * m];
            float2 acp = make_float2(a.x + c.x, a.y + c.y);
            float2 acm = make_float2(a.x - c.x, a.y - c.y);
            float2 bep = make_float2(b.x + e.x, b.y + e.y);
            float2 bem = make_float2(b.x - e.x, b.y - e.y);
            float2 u0 = make_float2(acp.x + bep.x, acp.y + bep.y);
            float2 u2 = make_float2(acp.x - bep.x, acp.y - bep.y);
            float2 u1 = make_float2(acm.x - s * bem.y, acm.y + s * bem.x);
            float2 u3 = make_float2(acm.x + s * bem.y, acm.y - s * bem.x);
            d[base] = u0;
            if (m == 1) {
                d[base + 1] = u1;
                d[base + 2] = u2;
                d[base + 3] = u3;
            } else {
                float2 w1 = tw[j * tws];
                float2 w2 = tw[2 * j * tws];
                float2 w3 = tw[3 * j * tws];
                float w1y = (sign > 0) ? -w1.y : w1.y;
                float w2y = (sign > 0) ? -w2.y : w2.y;
                float w3y = (sign > 0) ? -w3.y : w3.y;
                d[base + m]     = make_float2(u1.x * w1.x - u1.y * w1y, u1.x * w1y + u1.y * w1.x);
                d[base + 2 * m] = make_float2(u2.x * w2.x - u2.y * w2y, u2.x * w2y + u2.y * w2.x);
                d[base + 3 * m] = make_float2(u3.x * w3.x - u3.y * w3y, u3.x * w3y + u3.y * w3.x);
            }
        }
        __syncwarp();
    }
    if (LOG & 1) {
        float4* d4 = (float4*)d;
        for (int t = lane; t < (L >> 1); t += 32) {
            float4 v = d4[t];
            d4[t] = make_float4(v.x + v.z, v.y + v.w, v.x - v.z, v.y - v.w);
        }
        __syncwarp();
    }
}

// Fused small-band inverse FFT2 body (tile resident in smem).
template<int Q>
__device__ void fused_body(void* dynraw, float2* twbuf, int* invbuf,
                           size_t w_off, int batch, float* __restrict__ out,
                           size_t dst_base, size_t dst_cap, float scale) {
    float2* A = (float2*)dynraw;
    float2* B = A + Q * (Q + PADR);

    const int tid  = threadIdx.x;
    const int lane = tid & 31;
    const int w    = tid >> 5;
    const int nw   = blockDim.x >> 5;

    for (int i = tid; i < Q; i += blockDim.x) {
        float sn, cs;
        sincosf(-2.0f * PI_F * (float)i / (float)Q, &sn, &cs);
        twbuf[i] = make_float2(cs, sn);
        invbuf[digitrev<Q>(i)] = i;
    }
    __syncthreads();

    for (int i = tid; i < Q * Q; i += blockDim.x) {
        int r = i / Q, c = i % Q;
        A[r * (Q + PADR) + c] = g_P[w_off + (size_t)batch * Q * Q + i];
    }
    __syncthreads();

    for (int r = w; r < Q; r += nw) warp_fft4<Q>(A + r * (Q + PADR), twbuf, lane, +1);
    __syncthreads();

    for (int i = tid; i < Q * Q; i += blockDim.x) {
        int r = i / Q, c = i % Q;
        B[digitrev<Q>(c) * (Q + PADR) + r] = A[r * (Q + PADR) + c];
    }
    __syncthreads();

    for (int y = w; y < Q; y += nw) warp_fft4<Q>(B + y * (Q + PADR), twbuf, lane, +1);
    __syncthreads();

    for (int i = tid; i < Q * Q; i += blockDim.x) {
        int kk2 = i / Q, kk1 = i % Q;
        int c2 = invbuf[kk2];
        size_t o = dst_base + (size_t)batch * Q * Q + i;
        if (o < dst_cap) out[o] = B[kk1 * (Q + PADR) + c2].x * scale;
    }
}

// All four small-band inverse FFT2s in one launch (156 blocks).
__global__ void fused_all_kernel(float* __restrict__ out, size_t dst_cap) {
    extern __shared__ unsigned char dynraw[];
    __shared__ float2 twbuf[64];
    __shared__ int invbuf[64];
    const int b = blockIdx.x;
    if (b < 48)
        fused_body<64>(dynraw, twbuf, invbuf, OFF_W2, b, out, 7077888, dst_cap, 1.0f / 4096.0f);
    else if (b < 96)
        fused_body<32>(dynraw, twbuf, invbuf, OFF_W3, b - 48, out, 7274496, dst_cap, 1.0f / 1024.0f);
    else if (b < 144)
        fused_body<16>(dynraw, twbuf, invbuf, OFF_W4, b - 96, out, 7323648, dst_cap, 1.0f / 256.0f);
    else
        fused_body<16>(dynraw, twbuf, invbuf, OFF_WL, b - 144, out, 7335936, dst_cap, 1.0f / 256.0f);
}

// ============================================================================
// fold_all: all band folds + lowpass fold in ONE launch.
// ============================================================================
__device__ __forceinline__ void fold_body(int F, int Q, int bid0,
                                          const float* __restrict__ ang, size_t ang_cap,
                                          const float* __restrict__ sc_j, size_t sc_cap,
                                          size_t w_off) {
    int idx = (blockIdx.x - bid0) * blockDim.x + threadIdx.x;
    if (idx >= KANG * Q * Q) return;
    const int q2 = idx % Q;
    const int q1 = (idx / Q) % Q;
    const int k  = idx / (Q * Q);
    const size_t ang_off = (size_t)k * MM * MM;

    float2 acc[NIMG];
#pragma unroll
    for (int i = 0; i < NIMG; i++) acc[i] = make_float2(0.f, 0.f);
    const float invf2 = 1.0f / (float)(F * F);
    const float phc = PI_F * (float)(F - 1) / (float)MM;

    for (int r1 = 0; r1 < F; r1++) {
        const int k1 = q1 + Q * r1;
        const float c1 = cosf(PI_F * (float)k1 / (float)MM);
        const float ph1 = phc * (float)k1;
        for (int r2 = 0; r2 < F; r2++) {
            const int k2 = q2 + Q * r2;
            const size_t fidx = (size_t)k1 * MM + k2;
            const float s = (fidx < sc_cap) ? sc_j[fidx] : 0.0f;
            if (s == 0.0f) continue;
            const float a = (ang_off + fidx < ang_cap) ? ang[ang_off + fidx] : 0.0f;
            const float mg = s * a * invf2;
            if (mg == 0.0f) continue;
            const float c2 = cosf(PI_F * (float)k2 / (float)MM);
            float sp, cp;
            sincosf(ph1 + phc * (float)k2, &sp, &cp);
            const float m = mg * c1 * c2;
            const float2 wv = make_float2(m * cp, m * sp);
#pragma unroll
            for (int img = 0; img < NIMG; img++) {
                float2 xv = g_X[(size_t)img * (MM * MM) + fidx];
                acc[img].x += xv.x * wv.x - xv.y * wv.y;
                acc[img].y += xv.x * wv.y + xv.y * wv.x;
            }
        }
    }
#pragma unroll
    for (int img = 0; img < NIMG; img++) {
        size_t o = w_off + (((size_t)img * KANG + k) * Q + q1) * Q + q2;
        if (o < POOL_CAP) g_P[o] = acc[img];
    }
}

__device__ __forceinline__ void fold_low_body(const float* __restrict__ lp, size_t lp_cap,
                                              size_t w_off) {
    constexpr int F = 32, Q = 16;
    const int idx = threadIdx.x;
    const int q2 = idx & (Q - 1);
    const int q1 = idx >> 4;

    float2 acc[NIMG];
#pragma unroll
    for (int i = 0; i < NIMG; i++) acc[i] = make_float2(0.f, 0.f);
    const float invf2 = 1.0f / (float)(F * F);
    const float phc = PI_F * (float)(F - 1) / (float)MM;

    for (int r1 = 0; r1 < F; r1++) {
        const int k1 = q1 + Q * r1;
        const float c1 = cosf(PI_F * (float)k1 / (float)MM);
        const float ph1 = phc * (float)k1;
        for (int r2 = 0; r2 < F; r2++) {
            const int k2 = q2 + Q * r2;
            const size_t fidx = (size_t)k1 * MM + k2;
            const float s = (fidx < lp_cap) ? lp[fidx] : 0.0f;
            if (s == 0.0f) continue;
            const float c2 = cosf(PI_F * (float)k2 / (float)MM);
            float sp, cp;
            sincosf(ph1 + phc * (float)k2, &sp, &cp);
            const float m = s * invf2 * c1 * c2;
            const float2 wv = make_float2(m * cp, m * sp);
#pragma unroll
            for (int img = 0; img < NIMG; img++) {
                float2 xv = g_X[(size_t)img * (MM * MM) + fidx];
                acc[img].x += xv.x * wv.x - xv.y * wv.y;
                acc[img].y += xv.x * wv.y + xv.y * wv.x;
            }
        }
    }
#pragma unroll
    for (int img = 0; img < NIMG; img++) {
        size_t o = w_off + (size_t)img * (Q * Q) + q1 * Q + q2;
        if (o < POOL_CAP) g_P[o] = acc[img];
    }
}

__global__ void fold_all_kernel(const float* __restrict__ ang, size_t ang_cap,
                                const float* __restrict__ sc, size_t sc_cap,
                                const float* __restrict__ lp, size_t lp_cap) {
    const int b = blockIdx.x;
    const size_t scj = 262144u;
    if (b < 1024)
        fold_body(2, 256, 0, ang, ang_cap, sc, sc_cap, OFF_W0);
    else if (b < 1280)
        fold_body(4, 128, 1024, ang, ang_cap, sc + 1 * scj, sc_cap > 1 * scj ? sc_cap - 1 * scj : 0, OFF_W1);
    else if (b < 1344)
        fold_body(8, 64, 1280, ang, ang_cap, sc + 2 * scj, sc_cap > 2 * scj ? sc_cap - 2 * scj : 0, OFF_W2);
    else if (b < 1360)
        fold_body(16, 32, 1344, ang, ang_cap, sc + 3 * scj, sc_cap > 3 * scj ? sc_cap - 3 * scj : 0, OFF_W3);
    else if (b < 1364)
        fold_body(32, 16, 1360, ang, ang_cap, sc + 4 * scj, sc_cap > 4 * scj ? sc_cap - 4 * scj : 0, OFF_W4);
    else
        fold_low_body(lp, lp_cap, OFF_WL);
}

// ---------------------------------------------------------------------------
typedef int (*cuGetRange_t)(unsigned long long*, size_t*, unsigned long long);
static size_t dout_capacity_f(void* d_out, int out_size) {
    size_t bytes = 0;
    void* h = dlopen("libcuda.so.1", RTLD_NOW | RTLD_GLOBAL);
    if (!h) h = dlopen("libcuda.so", RTLD_NOW | RTLD_GLOBAL);
    if (h) {
        cuGetRange_t f = (cuGetRange_t)dlsym(h, "cuMemGetAddressRange_v2");
        if (!f) f = (cuGetRange_t)dlsym(h, "cuMemGetAddressRange");
        if (f) {
            unsigned long long base = 0; size_t sz = 0;
            if (f(&base, &sz, (unsigned long long)(uintptr_t)d_out) == 0 && sz > 0) {
                unsigned long long off = (unsigned long long)(uintptr_t)d_out - base;
                if (off < sz) bytes = sz - off;
            }
        }
    }
    if (bytes == 0) bytes = (size_t)out_size * 4u;
    size_t cap = bytes / 4u;
    if (cap > OUT_TOTAL) cap = OUT_TOTAL;
    return cap;
}

extern "C" void kernel_launch(void* const* d_in, const int* in_sizes, int n_in,
                              void* d_out, int out_size) {
    const float *x = nullptr, *hp = nullptr, *lp = nullptr, *ang = nullptr, *sc = nullptr;
    size_t xs = 0, hs = 0, ls = 0, as_ = 0, ss = 0;
    for (int i = 0; i < n_in; i++) {
        size_t s = (size_t)in_sizes[i];
        const float* p = (const float*)d_in[i];
        if (s == 3145728u && !x)        { x = p;  xs = s; }
        else if (s == 1048576u && !ang) { ang = p; as_ = s; }
        else if (s == 1310720u && !sc)  { sc = p; ss = s; }
        else if (s == 262144u) { if (!hp) { hp = p; hs = s; } else if (!lp) { lp = p; ls = s; } }
    }
    if (!x  && n_in > 0) { x  = (const float*)d_in[0]; xs  = (size_t)in_sizes[0]; }
    if (!hp && n_in > 1) { hp = (const float*)d_in[1]; hs  = (size_t)in_sizes[1]; }
    if (!lp && n_in > 2) { lp = (const float*)d_in[2]; ls  = (size_t)in_sizes[2]; }
    if (!ang&& n_in > 3) { ang= (const float*)d_in[3]; as_ = (size_t)in_sizes[3]; }
    if (!sc && n_in > 4) { sc = (const float*)d_in[4]; ss  = (size_t)in_sizes[4]; }

    float* outf = (float*)d_out;
    const size_t capf = dout_capacity_f(d_out, out_size);

    const int smFused = 2 * 64 * (64 + PADR) * 8;   // 67584
    cudaFuncSetAttribute(fused_all_kernel, cudaFuncAttributeMaxDynamicSharedMemorySize, smFused);

    const dim3 blk(256);

    // 1) forward FFT2 of x -> g_X  (R=16, L=512, 2 chunks -> 384 blocks)
    sfft_pass_kernel<16, 2, true , false><<<dim3(32, NIMG), blk>>>(
        x, xs, 0, 0, nullptr, 0, 0, 1, OFF_FT, nullptr, 0, -1, 1.0f);
    sfft_pass_kernel<16, 2, false, false><<<dim3(32, NIMG), blk>>>(
        nullptr, 0, 1, OFF_FT, nullptr, 0, 0, 0, 0, nullptr, 0, -1, 1.0f);

    // 2) highpass -> out0
    sfft_pass_kernel<16, 2, false, false><<<dim3(32, NIMG), blk>>>(
        nullptr, 0, 0, 0, nullptr, 0, 0, 1, OFF_FT, hp, hs, +1, 1.0f);
    sfft_pass_kernel<16, 2, false, true ><<<dim3(32, NIMG), blk>>>(
        nullptr, 0, 1, OFF_FT, outf, 0, capf, 0, 0, nullptr, 0, +1, 1.0f / 262144.0f);

    // 3) all folds in one launch
    fold_all_kernel<<<1365, blk>>>(ang, as_, sc, ss, lp, ls);

    // 4) j0 (Q=256, R=8, 4 chunks -> 384 blocks) -> out1
    sfft_pass_kernel<8, 4, false, false><<<dim3(8, 48), blk>>>(
        nullptr, 0, 1, OFF_W0, nullptr, 0, 0, 1, OFF_T0, nullptr, 0, +1, 1.0f);
    sfft_pass_kernel<8, 4, false, true ><<<dim3(8, 48), blk>>>(
        nullptr, 0, 1, OFF_T0, outf, 3145728, capf, 0, 0, nullptr, 0, +1, 1.0f / 65536.0f);

    // 5) j1 (Q=128, R=4, 2 chunks -> 384 blocks) -> out2
    sfft_pass_kernel<4, 2, false, false><<<dim3(8, 48), blk>>>(
        nullptr, 0, 1, OFF_W1, nullptr, 0, 0, 1, OFF_T1, nullptr, 0, +1, 1.0f);
    sfft_pass_kernel<4, 2, false, true ><<<dim3(8, 48), blk>>>(
        nullptr, 0, 1, OFF_T1, outf, 6291456, capf, 0, 0, nullptr, 0, +1, 1.0f / 16384.0f);

    // 6) all fused small bands in one launch
    fused_all_kernel<<<156, blk, smFused>>>(outf, capf);
}

// round 16
// speedup vs baseline: 1.0616x; 1.0616x over previous
#include <cuda_runtime.h>
#include <cstdint>
#include <dlfcn.h>

// ============================================================================
// Steerable pyramid, frequency-domain, M=N=512, B=4, C=3, K=4, S=5.
// OUTPUT = float32 REAL PARTS of each tuple element, concatenated (7339008 f32).
//
// 5 launches (independent stages merged via block-range dispatch):
//   1 fwd1: x -> FT            2 fwd2: FT -> g_X
//   3 A: [hp pass1 (g_X->FT)] || [all 5 band folds + lowpass fold -> W*]
//   4 B: [hp pass2 (FT->out0)] || [j0 pass1 W0->T0] || [j1 pass1 W1->T1]
//        || [fused ifft2 Q=64/32/16/16 -> out3..6]
//   5 C: [j0 pass2 T0->out1] || [j1 pass2 T1->out2]
//
// DIT shuffle FFT (L=32R): n = lane+32b (coalesced). Register FFT_R ->
// per-lane twiddle -> 5-stage shfl_xor FFT32. Staging smem XOR-swizzled.
// Fold alias-phase factors P[k]=cos(pi k/512) e^{i pi k(F-1)/512} from a
// per-block smem table (512 entries) - no per-term sincos.
// ============================================================================

#define MM 512
#define NIMG 12
#define KANG 4
#define PI_F 3.14159265358979323846f
#define PADR 2
#define FULLM 0xffffffffu

#define X_CAP    ((size_t)NIMG * MM * MM)
#define POOL_CAP ((size_t)11532288)
#define OUT_TOTAL ((size_t)7339008)

__device__ float2 g_X[NIMG * MM * MM];
__device__ float2 g_P[11532288];

#define OFF_FT   ((size_t)0)
#define OFF_W0   ((size_t)3145728)
#define OFF_T0   ((size_t)6291456)
#define OFF_W1   ((size_t)9437184)
#define OFF_T1   ((size_t)10223616)
#define OFF_W2   ((size_t)11010048)
#define OFF_W3   ((size_t)11403264)
#define OFF_W4   ((size_t)11501568)
#define OFF_WL   ((size_t)11526144)

__host__ __device__ constexpr int clog2(int n) { return n <= 1 ? 0 : 1 + clog2(n >> 1); }
__host__ __device__ constexpr int brevc(int x, int bits) {
    int r = 0;
    for (int i = 0; i < bits; i++) r = (r << 1) | ((x >> i) & 1);
    return r;
}

__device__ __forceinline__ float2 cmul(float2 a, float2 b) {
    return make_float2(a.x * b.x - a.y * b.y, a.x * b.y + a.y * b.x);
}

// ============================================================================
// DIT shuffle-FFT row pass body. smbuf: RPB*(L+1) + R float2 (dynamic smem).
// ============================================================================
template<int R, int CHUNKS, bool REAL_IN, bool REAL_OUT>
__device__ __forceinline__ void sfft_body(
    int bx, int batch, float2* smbuf,
    const float* __restrict__ ext_in, size_t src_cap, int src_sel, size_t src_off,
    float* __restrict__ ext_out, size_t dst_base, size_t dst_cap,
    int dst_sel, size_t dst_off,
    const float* __restrict__ filt, size_t filt_cap, int sign, float scale) {
    constexpr int L = 32 * R;
    constexpr int LOG_R = clog2(R);
    constexpr int RPB = 8;
    float2* twR = smbuf + RPB * (L + 1);

    const int tid  = threadIdx.x;
    const int lane = tid & 31;
    const int w    = tid >> 5;
    const float sg = (sign > 0) ? 1.0f : -1.0f;
    float2* smrow  = smbuf + w * (L + 1);

    if (tid < R) {
        float s, c;
        sincosf(sg * 2.0f * PI_F * (float)tid / (float)R, &s, &c);
        twR[tid] = make_float2(c, s);
    }
    float2 w32;
    {
        float s, c;
        sincosf(sg * 2.0f * PI_F * (float)(lane & 15) / 32.0f, &s, &c);
        w32 = make_float2(c, s);
    }
    float2 wl;
    {
        float s, c;
        sincosf(sg * 2.0f * PI_F * (float)lane / (float)L, &s, &c);
        wl = make_float2(c, s);
    }
    const int b5 = (int)(__brev((unsigned)lane) >> 27);
    __syncthreads();

    for (int ch = 0; ch < CHUNKS; ch++) {
        const int r0 = (bx * CHUNKS + ch) * RPB;
        const int r  = r0 + w;
        const size_t rowb = ((size_t)batch * L + r) * L;

        float2 v[R];
        if (REAL_IN) {
#pragma unroll
            for (int b = 0; b < R; b++) {
                size_t o = rowb + lane + 32 * b;
                float val = (o < src_cap) ? ext_in[o] : 0.0f;
                v[b] = make_float2(val, 0.0f);
            }
        } else {
            const float2* base = (src_sel == 0 ? g_X : g_P) + src_off;
            if (filt) {
                const size_t frow = (size_t)r * L + lane;
#pragma unroll
                for (int b = 0; b < R; b++) {
                    float2 t = base[rowb + lane + 32 * b];
                    float ff = (frow + 32 * b < filt_cap) ? filt[frow + 32 * b] : 0.0f;
                    v[b] = make_float2(t.x * ff, t.y * ff);
                }
            } else {
#pragma unroll
                for (int b = 0; b < R; b++) v[b] = base[rowb + lane + 32 * b];
            }
        }

        // register FFT_R (DIF; reg q holds k2 = brevc(q))
#pragma unroll
        for (int h2 = R / 2; h2 >= 1; h2 >>= 1) {
#pragma unroll
            for (int g = 0; g < R; g += 2 * h2) {
#pragma unroll
                for (int j = 0; j < h2; j++) {
                    float2 lo = v[g + j], hi2 = v[g + j + h2];
                    v[g + j] = make_float2(lo.x + hi2.x, lo.y + hi2.y);
                    float2 d = make_float2(lo.x - hi2.x, lo.y - hi2.y);
                    v[g + j + h2] = cmul(d, twR[j * (R / (2 * h2))]);
                }
            }
        }

        // twiddle: v[q] *= wl^{k2}, k2 = brevc(q)
        {
            float2 cur = wl;
#pragma unroll
            for (int k2 = 1; k2 < R; k2++) {
                if (k2 > 1) cur = cmul(cur, wl);
                const int qq = brevc(k2, LOG_R);
                v[qq] = cmul(v[qq], cur);
            }
        }

        // FFT32 across lanes (5 shfl_xor DIF stages)
#pragma unroll
        for (int st = 0; st < 5; st++) {
            const int h = 16 >> st;
            const int t = (lane & (h - 1)) * (16 / h);
            const float wre = __shfl_sync(FULLM, w32.x, t);
            const float wim = __shfl_sync(FULLM, w32.y, t);
            const bool hi = (lane & h) != 0;
#pragma unroll
            for (int b = 0; b < R; b++) {
                float ox = __shfl_xor_sync(FULLM, v[b].x, h);
                float oy = __shfl_xor_sync(FULLM, v[b].y, h);
                if (hi) {
                    float dx = ox - v[b].x, dy = oy - v[b].y;
                    v[b] = make_float2(dx * wre - dy * wim, dx * wim + dy * wre);
                } else {
                    v[b].x += ox; v[b].y += oy;
                }
            }
        }

        // stage to smem, natural order, XOR swizzle
#pragma unroll
        for (int q = 0; q < R; q++) {
            const int col = R * b5 + brevc(q, LOG_R);
            const int ph = col ^ ((col >> 4) & (R - 1));
            smrow[ph] = v[q];
        }
        __syncthreads();

        if (REAL_OUT) {
            for (int idx = tid; idx < RPB * L; idx += blockDim.x) {
                int rl = idx & (RPB - 1);
                int cc = idx >> 3;
                int ph = cc ^ ((cc >> 4) & (R - 1));
                size_t o = dst_base + ((size_t)batch * L + cc) * L + (r0 + rl);
                if (o < dst_cap) ext_out[o] = smbuf[rl * (L + 1) + ph].x * scale;
            }
        } else {
            float2* out = (dst_sel == 0 ? g_X : g_P);
            const size_t cap = (dst_sel == 0 ? X_CAP : POOL_CAP);
            for (int idx = tid; idx < RPB * L; idx += blockDim.x) {
                int rl = idx & (RPB - 1);
                int cc = idx >> 3;
                int ph = cc ^ ((cc >> 4) & (R - 1));
                float2 t = smbuf[rl * (L + 1) + ph];
                size_t o = dst_off + ((size_t)batch * L + cc) * L + (r0 + rl);
                if (o < cap) out[o] = make_float2(t.x * scale, t.y * scale);
            }
        }
        __syncthreads();
    }
}

// Standalone wrapper (forward passes).
template<int R, int CHUNKS, bool REAL_IN, bool REAL_OUT>
__global__ void __launch_bounds__(256) sfft_kernel(
    const float* __restrict__ ext_in, size_t src_cap, int src_sel, size_t src_off,
    float* __restrict__ ext_out, size_t dst_base, size_t dst_cap,
    int dst_sel, size_t dst_off,
    const float* __restrict__ filt, size_t filt_cap, int sign, float scale) {
    extern __shared__ unsigned char dyn[];
    sfft_body<R, CHUNKS, REAL_IN, REAL_OUT>(blockIdx.x, blockIdx.y, (float2*)dyn,
        ext_in, src_cap, src_sel, src_off, ext_out, dst_base, dst_cap,
        dst_sel, dst_off, filt, filt_cap, sign, scale);
}

// ============================================================================
// smem warp FFT for the fused small-band bodies
// ============================================================================
template<int L>
__device__ __forceinline__ int digitrev(int p) {
    constexpr int LOG = clog2(L);
    constexpr int NS4 = LOG >> 1;
    int k = 0;
    int shift = LOG;
#pragma unroll
    for (int s = 0; s < NS4; s++) {
        shift -= 2;
        k |= ((p >> shift) & 3) << (2 * s);
    }
    if (LOG & 1) k |= (p & 1) << (2 * NS4);
    return k;
}

template<int L>
__device__ __forceinline__ void warp_fft4(float2* d, const float2* tw, int lane, int sign) {
    constexpr int LOG = clog2(L);
    constexpr int NS4 = LOG >> 1;
    const float s = (sign > 0) ? 1.0f : -1.0f;
#pragma unroll
    for (int st = 0; st < NS4; st++) {
        const int m = L >> (2 + 2 * st);
        const int tws = 1 << (2 * st);
        for (int t = lane; t < (L >> 2); t += 32) {
            const int j = t & (m - 1);
            const int base = ((t & ~(m - 1)) << 2) + j;
            float2 a = d[base], b = d[base + m], c = d[base + 2 * m], e = d[base + 3 * m];
            float2 acp = make_float2(a.x + c.x, a.y + c.y);
            float2 acm = make_float2(a.x - c.x, a.y - c.y);
            float2 bep = make_float2(b.x + e.x, b.y + e.y);
            float2 bem = make_float2(b.x - e.x, b.y - e.y);
            float2 u0 = make_float2(acp.x + bep.x, acp.y + bep.y);
            float2 u2 = make_float2(acp.x - bep.x, acp.y - bep.y);
            float2 u1 = make_float2(acm.x - s * bem.y, acm.y + s * bem.x);
            float2 u3 = make_float2(acm.x + s * bem.y, acm.y - s * bem.x);
            d[base] = u0;
            if (m == 1) {
                d[base + 1] = u1;
                d[base + 2] = u2;
                d[base + 3] = u3;
            } else {
                float2 w1 = tw[j * tws];
                float2 w2 = tw[2 * j * tws];
                float2 w3 = tw[3 * j * tws];
                float w1y = (sign > 0) ? -w1.y : w1.y;
                float w2y = (sign > 0) ? -w2.y : w2.y;
                float w3y = (sign > 0) ? -w3.y : w3.y;
                d[base + m]     = make_float2(u1.x * w1.x - u1.y * w1y, u1.x * w1y + u1.y * w1.x);
                d[base + 2 * m] = make_float2(u2.x * w2.x - u2.y * w2y, u2.x * w2y + u2.y * w2.x);
                d[base + 3 * m] = make_float2(u3.x * w3.x - u3.y * w3y, u3.x * w3y + u3.y * w3.x);
            }
        }
        __syncwarp();
    }
    if (LOG & 1) {
        float4* d4 = (float4*)d;
        for (int t = lane; t < (L >> 1); t += 32) {
            float4 v = d4[t];
            d4[t] = make_float4(v.x + v.z, v.y + v.w, v.x - v.z, v.y - v.w);
        }
        __syncwarp();
    }
}

template<int Q>
__device__ void fused_body(void* dynraw, float2* twbuf, int* invbuf,
                           size_t w_off, int batch, float* __restrict__ out,
                           size_t dst_base, size_t dst_cap, float scale) {
    float2* A = (float2*)dynraw;
    float2* B = A + Q * (Q + PADR);

    const int tid  = threadIdx.x;
    const int lane = tid & 31;
    const int w    = tid >> 5;
    const int nw   = blockDim.x >> 5;

    for (int i = tid; i < Q; i += blockDim.x) {
        float sn, cs;
        sincosf(-2.0f * PI_F * (float)i / (float)Q, &sn, &cs);
        twbuf[i] = make_float2(cs, sn);
        invbuf[digitrev<Q>(i)] = i;
    }
    __syncthreads();

    for (int i = tid; i < Q * Q; i += blockDim.x) {
        int r = i / Q, c = i % Q;
        A[r * (Q + PADR) + c] = g_P[w_off + (size_t)batch * Q * Q + i];
    }
    __syncthreads();

    for (int r = w; r < Q; r += nw) warp_fft4<Q>(A + r * (Q + PADR), twbuf, lane, +1);
    __syncthreads();

    for (int i = tid; i < Q * Q; i += blockDim.x) {
        int r = i / Q, c = i % Q;
        B[digitrev<Q>(c) * (Q + PADR) + r] = A[r * (Q + PADR) + c];
    }
    __syncthreads();

    for (int y = w; y < Q; y += nw) warp_fft4<Q>(B + y * (Q + PADR), twbuf, lane, +1);
    __syncthreads();

    for (int i = tid; i < Q * Q; i += blockDim.x) {
        int kk2 = i / Q, kk1 = i % Q;
        int c2 = invbuf[kk2];
        size_t o = dst_base + (size_t)batch * Q * Q + i;
        if (o < dst_cap) out[o] = B[kk1 * (Q + PADR) + c2].x * scale;
    }
}

// ============================================================================
// Fold bodies with per-block P-table: P[k] = cos(pi k/512) e^{i pi k (F-1)/512}
// ============================================================================
__device__ __forceinline__ void build_ptab(int F, float2* Ptab) {
    for (int i = threadIdx.x; i < MM; i += blockDim.x) {
        float c = cosf(PI_F * (float)i / (float)MM);
        float sph, cph;
        sincosf(PI_F * (float)(F - 1) * (float)i / (float)MM, &sph, &cph);
        Ptab[i] = make_float2(c * cph, c * sph);
    }
    __syncthreads();
}

__device__ __forceinline__ void fold_body(int F, int Q, int bidLocal,
                                          const float* __restrict__ ang, size_t ang_cap,
                                          const float* __restrict__ sc_j, size_t sc_cap,
                                          size_t w_off, float2* Ptab) {
    build_ptab(F, Ptab);
    int idx = bidLocal * blockDim.x + threadIdx.x;
    if (idx >= KANG * Q * Q) return;
    const int q2 = idx % Q;
    const int q1 = (idx / Q) % Q;
    const int k  = idx / (Q * Q);
    const size_t ang_off = (size_t)k * MM * MM;

    float2 acc[NIMG];
#pragma unroll
    for (int i = 0; i < NIMG; i++) acc[i] = make_float2(0.f, 0.f);
    const float invf2 = 1.0f / (float)(F * F);

    for (int r1 = 0; r1 < F; r1++) {
        const int k1 = q1 + Q * r1;
        const float2 p1 = Ptab[k1];
        for (int r2 = 0; r2 < F; r2++) {
            const int k2 = q2 + Q * r2;
            const size_t fidx = (size_t)k1 * MM + k2;
            const float s = (fidx < sc_cap) ? sc_j[fidx] : 0.0f;
            if (s == 0.0f) continue;
            const float a = (ang_off + fidx < ang_cap) ? ang[ang_off + fidx] : 0.0f;
            const float mg = s * a * invf2;
            if (mg == 0.0f) continue;
            float2 pf = cmul(p1, Ptab[k2]);
            const float2 wv = make_float2(mg * pf.x, mg * pf.y);
#pragma unroll
            for (int img = 0; img < NIMG; img++) {
                float2 xv = g_X[(size_t)img * (MM * MM) + fidx];
                acc[img].x += xv.x * wv.x - xv.y * wv.y;
                acc[img].y += xv.x * wv.y + xv.y * wv.x;
            }
        }
    }
#pragma unroll
    for (int img = 0; img < NIMG; img++) {
        size_t o = w_off + (((size_t)img * KANG + k) * Q + q1) * Q + q2;
        if (o < POOL_CAP) g_P[o] = acc[img];
    }
}

__device__ __forceinline__ void fold_low_body(const float* __restrict__ lp, size_t lp_cap,
                                              size_t w_off, float2* Ptab) {
    constexpr int F = 32, Q = 16;
    build_ptab(F, Ptab);
    const int idx = threadIdx.x;
    const int q2 = idx & (Q - 1);
    const int q1 = idx >> 4;

    float2 acc[NIMG];
#pragma unroll
    for (int i = 0; i < NIMG; i++) acc[i] = make_float2(0.f, 0.f);
    const float invf2 = 1.0f / (float)(F * F);

    for (int r1 = 0; r1 < F; r1++) {
        const int k1 = q1 + Q * r1;
        const float2 p1 = Ptab[k1];
        for (int r2 = 0; r2 < F; r2++) {
            const int k2 = q2 + Q * r2;
            const size_t fidx = (size_t)k1 * MM + k2;
            const float s = (fidx < lp_cap) ? lp[fidx] : 0.0f;
            if (s == 0.0f) continue;
            float2 pf = cmul(p1, Ptab[k2]);
            const float m = s * invf2;
            const float2 wv = make_float2(m * pf.x, m * pf.y);
#pragma unroll
            for (int img = 0; img < NIMG; img++) {
                float2 xv = g_X[(size_t)img * (MM * MM) + fidx];
                acc[img].x += xv.x * wv.x - xv.y * wv.y;
                acc[img].y += xv.x * wv.y + xv.y * wv.x;
            }
        }
    }
#pragma unroll
    for (int img = 0; img < NIMG; img++) {
        size_t o = w_off + (size_t)img * (Q * Q) + q1 * Q + q2;
        if (o < POOL_CAP) g_P[o] = acc[img];
    }
}

// ============================================================================
// Merged launches
// ============================================================================
// A: blocks [0,384): hp pass1 (g_X -> FT); [384,1749): folds
__global__ void __launch_bounds__(256) kernelA(
    const float* __restrict__ hp, size_t hs,
    const float* __restrict__ ang, size_t as_,
    const float* __restrict__ sc, size_t ss,
    const float* __restrict__ lp, size_t ls) {
    extern __shared__ unsigned char dyn[];
    __shared__ float2 Ptab[MM];
    const int b = blockIdx.x;
    const size_t scj = 262144u;
    if (b < 384) {
        sfft_body<16, 2, false, false>(b & 31, b >> 5, (float2*)dyn,
            nullptr, 0, 0, 0, nullptr, 0, 0, 1, OFF_FT, hp, hs, +1, 1.0f);
    } else {
        int fb = b - 384;
        if (fb < 1024)
            fold_body(2, 256, fb, ang, as_, sc, ss, OFF_W0, Ptab);
        else if (fb < 1280)
            fold_body(4, 128, fb - 1024, ang, as_, sc + scj, ss > scj ? ss - scj : 0, OFF_W1, Ptab);
        else if (fb < 1344)
            fold_body(8, 64, fb - 1280, ang, as_, sc + 2 * scj, ss > 2 * scj ? ss - 2 * scj : 0, OFF_W2, Ptab);
        else if (fb < 1360)
            fold_body(16, 32, fb - 1344, ang, as_, sc + 3 * scj, ss > 3 * scj ? ss - 3 * scj : 0, OFF_W3, Ptab);
        else if (fb < 1364)
            fold_body(32, 16, fb - 1360, ang, as_, sc + 4 * scj, ss > 4 * scj ? ss - 4 * scj : 0, OFF_W4, Ptab);
        else
            fold_low_body(lp, ls, OFF_WL, Ptab);
    }
}

// B: [0,384) hp pass2 -> out0; [384,768) j0 pass1; [768,1152) j1 pass1;
//    [1152,1308) fused small bands -> out3..6
__global__ void __launch_bounds__(256) kernelB(float* __restrict__ outf, size_t capf) {
    extern __shared__ unsigned char dyn[];
    __shared__ float2 twbuf[64];
    __shared__ int invbuf[64];
    const int b = blockIdx.x;
    if (b < 384) {
        sfft_body<16, 2, false, true>(b & 31, b >> 5, (float2*)dyn,
            nullptr, 0, 1, OFF_FT, outf, 0, capf, 0, 0, nullptr, 0, +1, 1.0f / 262144.0f);
    } else if (b < 768) {
        int bb = b - 384;
        sfft_body<8, 4, false, false>(bb & 7, bb >> 3, (float2*)dyn,
            nullptr, 0, 1, OFF_W0, nullptr, 0, 0, 1, OFF_T0, nullptr, 0, +1, 1.0f);
    } else if (b < 1152) {
        int bb = b - 768;
        sfft_body<4, 2, false, false>(bb & 7, bb >> 3, (float2*)dyn,
            nullptr, 0, 1, OFF_W1, nullptr, 0, 0, 1, OFF_T1, nullptr, 0, +1, 1.0f);
    } else {
        int fb = b - 1152;
        if (fb < 48)
            fused_body<64>(dyn, twbuf, invbuf, OFF_W2, fb, outf, 7077888, capf, 1.0f / 4096.0f);
        else if (fb < 96)
            fused_body<32>(dyn, twbuf, invbuf, OFF_W3, fb - 48, outf, 7274496, capf, 1.0f / 1024.0f);
        else if (fb < 144)
            fused_body<16>(dyn, twbuf, invbuf, OFF_W4, fb - 96, outf, 7323648, capf, 1.0f / 256.0f);
        else
            fused_body<16>(dyn, twbuf, invbuf, OFF_WL, fb - 144, outf, 7335936, capf, 1.0f / 256.0f);
    }
}

// C: [0,384) j0 pass2 -> out1; [384,768) j1 pass2 -> out2
__global__ void __launch_bounds__(256) kernelC(float* __restrict__ outf, size_t capf) {
    extern __shared__ unsigned char dyn[];
    const int b = blockIdx.x;
    if (b < 384) {
        sfft_body<8, 4, false, true>(b & 7, b >> 3, (float2*)dyn,
            nullptr, 0, 1, OFF_T0, outf, 3145728, capf, 0, 0, nullptr, 0, +1, 1.0f / 65536.0f);
    } else {
        int bb = b - 384;
        sfft_body<4, 2, false, true>(bb & 7, bb >> 3, (float2*)dyn,
            nullptr, 0, 1, OFF_T1, outf, 6291456, capf, 0, 0, nullptr, 0, +1, 1.0f / 16384.0f);
    }
}

// ---------------------------------------------------------------------------
typedef int (*cuGetRange_t)(unsigned long long*, size_t*, unsigned long long);
static size_t dout_capacity_f(void* d_out, int out_size) {
    size_t bytes = 0;
    void* h = dlopen("libcuda.so.1", RTLD_NOW | RTLD_GLOBAL);
    if (!h) h = dlopen("libcuda.so", RTLD_NOW | RTLD_GLOBAL);
    if (h) {
        cuGetRange_t f = (cuGetRange_t)dlsym(h, "cuMemGetAddressRange_v2");
        if (!f) f = (cuGetRange_t)dlsym(h, "cuMemGetAddressRange");
        if (f) {
            unsigned long long base = 0; size_t sz = 0;
            if (f(&base, &sz, (unsigned long long)(uintptr_t)d_out) == 0 && sz > 0) {
                unsigned long long off = (unsigned long long)(uintptr_t)d_out - base;
                if (off < sz) bytes = sz - off;
            }
        }
    }
    if (bytes == 0) bytes = (size_t)out_size * 4u;
    size_t cap = bytes / 4u;
    if (cap > OUT_TOTAL) cap = OUT_TOTAL;
    return cap;
}

extern "C" void kernel_launch(void* const* d_in, const int* in_sizes, int n_in,
                              void* d_out, int out_size) {
    const float *x = nullptr, *hp = nullptr, *lp = nullptr, *ang = nullptr, *sc = nullptr;
    size_t xs = 0, hs = 0, ls = 0, as_ = 0, ss = 0;
    for (int i = 0; i < n_in; i++) {
        size_t s = (size_t)in_sizes[i];
        const float* p = (const float*)d_in[i];
        if (s == 3145728u && !x)        { x = p;  xs = s; }
        else if (s == 1048576u && !ang) { ang = p; as_ = s; }
        else if (s == 1310720u && !sc)  { sc = p; ss = s; }
        else if (s == 262144u) { if (!hp) { hp = p; hs = s; } else if (!lp) { lp = p; ls = s; } }
    }
    if (!x  && n_in > 0) { x  = (const float*)d_in[0]; xs  = (size_t)in_sizes[0]; }
    if (!hp && n_in > 1) { hp = (const float*)d_in[1]; hs  = (size_t)in_sizes[1]; }
    if (!lp && n_in > 2) { lp = (const float*)d_in[2]; ls  = (size_t)in_sizes[2]; }
    if (!ang&& n_in > 3) { ang= (const float*)d_in[3]; as_ = (size_t)in_sizes[3]; }
    if (!sc && n_in > 4) { sc = (const float*)d_in[4]; ss  = (size_t)in_sizes[4]; }

    float* outf = (float*)d_out;
    const size_t capf = dout_capacity_f(d_out, out_size);

    // dynamic smem: sfft L=512 needs (8*513+16)*8 = 32960 B
    const int smL512 = (8 * 513 + 16) * 8;           // 32960
    const int smB    = 2 * 64 * (64 + PADR) * 8;     // 67584 (fused Q=64 dominates B)
    const int smC    = (8 * 257 + 8) * 8;            // 16512

    cudaFuncSetAttribute(kernelB, cudaFuncAttributeMaxDynamicSharedMemorySize, smB);

    const dim3 blk(256);

    // 1-2) forward FFT2 of x -> g_X
    sfft_kernel<16, 2, true , false><<<dim3(32, NIMG), blk, smL512>>>(
        x, xs, 0, 0, nullptr, 0, 0, 1, OFF_FT, nullptr, 0, -1, 1.0f);
    sfft_kernel<16, 2, false, false><<<dim3(32, NIMG), blk, smL512>>>(
        nullptr, 0, 1, OFF_FT, nullptr, 0, 0, 0, 0, nullptr, 0, -1, 1.0f);

    // 3) A: hp pass1 || all folds
    kernelA<<<1749, blk, smL512>>>(hp, hs, ang, as_, sc, ss, lp, ls);

    // 4) B: hp pass2 || j0 pass1 || j1 pass1 || fused small bands
    kernelB<<<1308, blk, smB>>>(outf, capf);

    // 5) C: j0 pass2 || j1 pass2
    kernelC<<<768, blk, smC>>>(outf, capf);
}

// round 17
// speedup vs baseline: 1.0617x; 1.0001x over previous
#include <cuda_runtime.h>
#include <cstdint>
#include <dlfcn.h>

// ============================================================================
// Steerable pyramid, frequency-domain, M=N=512, B=4, C=3, K=4, S=5.
// OUTPUT = float32 REAL PARTS of each tuple element, concatenated (7339008 f32).
//
// 5 launches (independent stages merged via block-range dispatch):
//   1 fwd1: x -> FT            2 fwd2: FT -> g_X
//   3 A: [hp pass1 (g_X->FT)] || [all 5 band folds + lowpass fold -> W*]
//   4 B: [hp pass2 (FT->out0)] || [j0 pass1 W0->T0] || [j1 pass1 W1->T1]
//        || [fused ifft2 Q=64/32/16/16 -> out3..6]
//   5 C: [j0 pass2 T0->out1] || [j1 pass2 T1->out2]
//
// DIT shuffle FFT (L=32R): n = lane+32b (coalesced). Register FFT_R ->
// per-lane twiddle -> 5-stage shfl_xor FFT32. Staging smem XOR-swizzled.
// Fold alias-phase factors P[k]=cos(pi k/512) e^{i pi k(F-1)/512} from a
// per-block smem table (512 entries) - no per-term sincos.
// ============================================================================

#define MM 512
#define NIMG 12
#define KANG 4
#define PI_F 3.14159265358979323846f
#define PADR 2
#define FULLM 0xffffffffu

#define X_CAP    ((size_t)NIMG * MM * MM)
#define POOL_CAP ((size_t)11532288)
#define OUT_TOTAL ((size_t)7339008)

__device__ float2 g_X[NIMG * MM * MM];
__device__ float2 g_P[11532288];

#define OFF_FT   ((size_t)0)
#define OFF_W0   ((size_t)3145728)
#define OFF_T0   ((size_t)6291456)
#define OFF_W1   ((size_t)9437184)
#define OFF_T1   ((size_t)10223616)
#define OFF_W2   ((size_t)11010048)
#define OFF_W3   ((size_t)11403264)
#define OFF_W4   ((size_t)11501568)
#define OFF_WL   ((size_t)11526144)

__host__ __device__ constexpr int clog2(int n) { return n <= 1 ? 0 : 1 + clog2(n >> 1); }
__host__ __device__ constexpr int brevc(int x, int bits) {
    int r = 0;
    for (int i = 0; i < bits; i++) r = (r << 1) | ((x >> i) & 1);
    return r;
}

__device__ __forceinline__ float2 cmul(float2 a, float2 b) {
    return make_float2(a.x * b.x - a.y * b.y, a.x * b.y + a.y * b.x);
}

// ============================================================================
// DIT shuffle-FFT row pass body. smbuf: RPB*(L+1) + R float2 (dynamic smem).
// ============================================================================
template<int R, int CHUNKS, bool REAL_IN, bool REAL_OUT>
__device__ __forceinline__ void sfft_body(
    int bx, int batch, float2* smbuf,
    const float* __restrict__ ext_in, size_t src_cap, int src_sel, size_t src_off,
    float* __restrict__ ext_out, size_t dst_base, size_t dst_cap,
    int dst_sel, size_t dst_off,
    const float* __restrict__ filt, size_t filt_cap, int sign, float scale) {
    constexpr int L = 32 * R;
    constexpr int LOG_R = clog2(R);
    constexpr int RPB = 8;
    float2* twR = smbuf + RPB * (L + 1);

    const int tid  = threadIdx.x;
    const int lane = tid & 31;
    const int w    = tid >> 5;
    const float sg = (sign > 0) ? 1.0f : -1.0f;
    float2* smrow  = smbuf + w * (L + 1);

    if (tid < R) {
        float s, c;
        sincosf(sg * 2.0f * PI_F * (float)tid / (float)R, &s, &c);
        twR[tid] = make_float2(c, s);
    }
    float2 w32;
    {
        float s, c;
        sincosf(sg * 2.0f * PI_F * (float)(lane & 15) / 32.0f, &s, &c);
        w32 = make_float2(c, s);
    }
    float2 wl;
    {
        float s, c;
        sincosf(sg * 2.0f * PI_F * (float)lane / (float)L, &s, &c);
        wl = make_float2(c, s);
    }
    const int b5 = (int)(__brev((unsigned)lane) >> 27);
    __syncthreads();

    for (int ch = 0; ch < CHUNKS; ch++) {
        const int r0 = (bx * CHUNKS + ch) * RPB;
        const int r  = r0 + w;
        const size_t rowb = ((size_t)batch * L + r) * L;

        float2 v[R];
        if (REAL_IN) {
#pragma unroll
            for (int b = 0; b < R; b++) {
                size_t o = rowb + lane + 32 * b;
                float val = (o < src_cap) ? ext_in[o] : 0.0f;
                v[b] = make_float2(val, 0.0f);
            }
        } else {
            const float2* base = (src_sel == 0 ? g_X : g_P) + src_off;
            if (filt) {
                const size_t frow = (size_t)r * L + lane;
#pragma unroll
                for (int b = 0; b < R; b++) {
                    float2 t = base[rowb + lane + 32 * b];
                    float ff = (frow + 32 * b < filt_cap) ? filt[frow + 32 * b] : 0.0f;
                    v[b] = make_float2(t.x * ff, t.y * ff);
                }
            } else {
#pragma unroll
                for (int b = 0; b < R; b++) v[b] = base[rowb + lane + 32 * b];
            }
        }

        // register FFT_R (DIF; reg q holds k2 = brevc(q))
#pragma unroll
        for (int h2 = R / 2; h2 >= 1; h2 >>= 1) {
#pragma unroll
            for (int g = 0; g < R; g += 2 * h2) {
#pragma unroll
                for (int j = 0; j < h2; j++) {
                    float2 lo = v[g + j], hi2 = v[g + j + h2];
                    v[g + j] = make_float2(lo.x + hi2.x, lo.y + hi2.y);
                    float2 d = make_float2(lo.x - hi2.x, lo.y - hi2.y);
                    v[g + j + h2] = cmul(d, twR[j * (R / (2 * h2))]);
                }
            }
        }

        // twiddle: v[q] *= wl^{k2}, k2 = brevc(q)
        {
            float2 cur = wl;
#pragma unroll
            for (int k2 = 1; k2 < R; k2++) {
                if (k2 > 1) cur = cmul(cur, wl);
                const int qq = brevc(k2, LOG_R);
                v[qq] = cmul(v[qq], cur);
            }
        }

        // FFT32 across lanes (5 shfl_xor DIF stages)
#pragma unroll
        for (int st = 0; st < 5; st++) {
            const int h = 16 >> st;
            const int t = (lane & (h - 1)) * (16 / h);
            const float wre = __shfl_sync(FULLM, w32.x, t);
            const float wim = __shfl_sync(FULLM, w32.y, t);
            const bool hi = (lane & h) != 0;
#pragma unroll
            for (int b = 0; b < R; b++) {
                float ox = __shfl_xor_sync(FULLM, v[b].x, h);
                float oy = __shfl_xor_sync(FULLM, v[b].y, h);
                if (hi) {
                    float dx = ox - v[b].x, dy = oy - v[b].y;
                    v[b] = make_float2(dx * wre - dy * wim, dx * wim + dy * wre);
                } else {
                    v[b].x += ox; v[b].y += oy;
                }
            }
        }

        // stage to smem, natural order, XOR swizzle
#pragma unroll
        for (int q = 0; q < R; q++) {
            const int col = R * b5 + brevc(q, LOG_R);
            const int ph = col ^ ((col >> 4) & (R - 1));
            smrow[ph] = v[q];
        }
        __syncthreads();

        if (REAL_OUT) {
            for (int idx = tid; idx < RPB * L; idx += blockDim.x) {
                int rl = idx & (RPB - 1);
                int cc = idx >> 3;
                int ph = cc ^ ((cc >> 4) & (R - 1));
                size_t o = dst_base + ((size_t)batch * L + cc) * L + (r0 + rl);
                if (o < dst_cap) ext_out[o] = smbuf[rl * (L + 1) + ph].x * scale;
            }
        } else {
            float2* out = (dst_sel == 0 ? g_X : g_P);
            const size_t cap = (dst_sel == 0 ? X_CAP : POOL_CAP);
            for (int idx = tid; idx < RPB * L; idx += blockDim.x) {
                int rl = idx & (RPB - 1);
                int cc = idx >> 3;
                int ph = cc ^ ((cc >> 4) & (R - 1));
                float2 t = smbuf[rl * (L + 1) + ph];
                size_t o = dst_off + ((size_t)batch * L + cc) * L + (r0 + rl);
                if (o < cap) out[o] = make_float2(t.x * scale, t.y * scale);
            }
        }
        __syncthreads();
    }
}

// Standalone wrapper (forward passes).
template<int R, int CHUNKS, bool REAL_IN, bool REAL_OUT>
__global__ void __launch_bounds__(256) sfft_kernel(
    const float* __restrict__ ext_in, size_t src_cap, int src_sel, size_t src_off,
    float* __restrict__ ext_out, size_t dst_base, size_t dst_cap,
    int dst_sel, size_t dst_off,
    const float* __restrict__ filt, size_t filt_cap, int sign, float scale) {
    extern __shared__ unsigned char dyn[];
    sfft_body<R, CHUNKS, REAL_IN, REAL_OUT>(blockIdx.x, blockIdx.y, (float2*)dyn,
        ext_in, src_cap, src_sel, src_off, ext_out, dst_base, dst_cap,
        dst_sel, dst_off, filt, filt_cap, sign, scale);
}

// ============================================================================
// smem warp FFT for the fused small-band bodies
// ============================================================================
template<int L>
__device__ __forceinline__ int digitrev(int p) {
    constexpr int LOG = clog2(L);
    constexpr int NS4 = LOG >> 1;
    int k = 0;
    int shift = LOG;
#pragma unroll
    for (int s = 0; s < NS4; s++) {
        shift -= 2;
        k |= ((p >> shift) & 3) << (2 * s);
    }
    if (LOG & 1) k |= (p & 1) << (2 * NS4);
    return k;
}

template<int L>
__device__ __forceinline__ void warp_fft4(float2* d, const float2* tw, int lane, int sign) {
    constexpr int LOG = clog2(L);
    constexpr int NS4 = LOG >> 1;
    const float s = (sign > 0) ? 1.0f : -1.0f;
#pragma unroll
    for (int st = 0; st < NS4; st++) {
        const int m = L >> (2 + 2 * st);
        const int tws = 1 << (2 * st);
        for (int t = lane; t < (L >> 2); t += 32) {
            const int j = t & (m - 1);
            const int base = ((t & ~(m - 1)) << 2) + j;
            float2 a = d[base], b = d[base + m], c = d[base + 2 * m], e = d[base + 3 * m];
            float2 acp = make_float2(a.x + c.x, a.y + c.y);
            float2 acm = make_float2(a.x - c.x, a.y - c.y);
            float2 bep = make_float2(b.x + e.x, b.y + e.y);
            float2 bem = make_float2(b.x - e.x, b.y - e.y);
            float2 u0 = make_float2(acp.x + bep.x, acp.y + bep.y);
            float2 u2 = make_float2(acp.x - bep.x, acp.y - bep.y);
            float2 u1 = make_float2(acm.x - s * bem.y, acm.y + s * bem.x);
            float2 u3 = make_float2(acm.x + s * bem.y, acm.y - s * bem.x);
            d[base] = u0;
            if (m == 1) {
                d[base + 1] = u1;
                d[base + 2] = u2;
                d[base + 3] = u3;
            } else {
                float2 w1 = tw[j * tws];
                float2 w2 = tw[2 * j * tws];
                float2 w3 = tw[3 * j * tws];
                float w1y = (sign > 0) ? -w1.y : w1.y;
                float w2y = (sign > 0) ? -w2.y : w2.y;
                float w3y = (sign > 0) ? -w3.y : w3.y;
                d[base + m]     = make_float2(u1.x * w1.x - u1.y * w1y, u1.x * w1y + u1.y * w1.x);
                d[base + 2 * m] = make_float2(u2.x * w2.x - u2.y * w2y, u2.x * w2y + u2.y * w2.x);
                d[base + 3 * m] = make_float2(u3.x * w3.x - u3.y * w3y, u3.x * w3y + u3.y * w3.x);
            }
        }
        __syncwarp();
    }
    if (LOG & 1) {
        float4* d4 = (float4*)d;
        for (int t = lane; t < (L >> 1); t += 32) {
            float4 v = d4[t];
            d4[t] = make_float4(v.x + v.z, v.y + v.w, v.x - v.z, v.y - v.w);
        }
        __syncwarp();
    }
}

template<int Q>
__device__ void fused_body(void* dynraw, float2* twbuf, int* invbuf,
                           size_t w_off, int batch, float* __restrict__ out,
                           size_t dst_base, size_t dst_cap, float scale) {
    float2* A = (float2*)dynraw;
    float2* B = A + Q * (Q + PADR);

    const int tid  = threadIdx.x;
    const int lane = tid & 31;
    const int w    = tid >> 5;
    const int nw   = blockDim.x >> 5;

    for (int i = tid; i < Q; i += blockDim.x) {
        float sn, cs;
        sincosf(-2.0f * PI_F * (float)i / (float)Q, &sn, &cs);
        twbuf[i] = make_float2(cs, sn);
        invbuf[digitrev<Q>(i)] = i;
    }
    __syncthreads();

    for (int i = tid; i < Q * Q; i += blockDim.x) {
        int r = i / Q, c = i % Q;
        A[r * (Q + PADR) + c] = g_P[w_off + (size_t)batch * Q * Q + i];
    }
    __syncthreads();

    for (int r = w; r < Q; r += nw) warp_fft4<Q>(A + r * (Q + PADR), twbuf, lane, +1);
    __syncthreads();

    for (int i = tid; i < Q * Q; i += blockDim.x) {
        int r = i / Q, c = i % Q;
        B[digitrev<Q>(c) * (Q + PADR) + r] = A[r * (Q + PADR) + c];
    }
    __syncthreads();

    for (int y = w; y < Q; y += nw) warp_fft4<Q>(B + y * (Q + PADR), twbuf, lane, +1);
    __syncthreads();

    for (int i = tid; i < Q * Q; i += blockDim.x) {
        int kk2 = i / Q, kk1 = i % Q;
        int c2 = invbuf[kk2];
        size_t o = dst_base + (size_t)batch * Q * Q + i;
        if (o < dst_cap) out[o] = B[kk1 * (Q + PADR) + c2].x * scale;
    }
}

// ============================================================================
// Fold bodies with per-block P-table: P[k] = cos(pi k/512) e^{i pi k (F-1)/512}
// ============================================================================
__device__ __forceinline__ void build_ptab(int F, float2* Ptab) {
    for (int i = threadIdx.x; i < MM; i += blockDim.x) {
        float c = cosf(PI_F * (float)i / (float)MM);
        float sph, cph;
        sincosf(PI_F * (float)(F - 1) * (float)i / (float)MM, &sph, &cph);
        Ptab[i] = make_float2(c * cph, c * sph);
    }
    __syncthreads();
}

__device__ __forceinline__ void fold_body(int F, int Q, int bidLocal,
                                          const float* __restrict__ ang, size_t ang_cap,
                                          const float* __restrict__ sc_j, size_t sc_cap,
                                          size_t w_off, float2* Ptab) {
    build_ptab(F, Ptab);
    int idx = bidLocal * blockDim.x + threadIdx.x;
    if (idx >= KANG * Q * Q) return;
    const int q2 = idx % Q;
    const int q1 = (idx / Q) % Q;
    const int k  = idx / (Q * Q);
    const size_t ang_off = (size_t)k * MM * MM;

    float2 acc[NIMG];
#pragma unroll
    for (int i = 0; i < NIMG; i++) acc[i] = make_float2(0.f, 0.f);
    const float invf2 = 1.0f / (float)(F * F);

    for (int r1 = 0; r1 < F; r1++) {
        const int k1 = q1 + Q * r1;
        const float2 p1 = Ptab[k1];
        for (int r2 = 0; r2 < F; r2++) {
            const int k2 = q2 + Q * r2;
            const size_t fidx = (size_t)k1 * MM + k2;
            const float s = (fidx < sc_cap) ? sc_j[fidx] : 0.0f;
            if (s == 0.0f) continue;
            const float a = (ang_off + fidx < ang_cap) ? ang[ang_off + fidx] : 0.0f;
            const float mg = s * a * invf2;
            if (mg == 0.0f) continue;
            float2 pf = cmul(p1, Ptab[k2]);
            const float2 wv = make_float2(mg * pf.x, mg * pf.y);
#pragma unroll
            for (int img = 0; img < NIMG; img++) {
                float2 xv = g_X[(size_t)img * (MM * MM) + fidx];
                acc[img].x += xv.x * wv.x - xv.y * wv.y;
                acc[img].y += xv.x * wv.y + xv.y * wv.x;
            }
        }
    }
#pragma unroll
    for (int img = 0; img < NIMG; img++) {
        size_t o = w_off + (((size_t)img * KANG + k) * Q + q1) * Q + q2;
        if (o < POOL_CAP) g_P[o] = acc[img];
    }
}

__device__ __forceinline__ void fold_low_body(const float* __restrict__ lp, size_t lp_cap,
                                              size_t w_off, float2* Ptab) {
    constexpr int F = 32, Q = 16;
    build_ptab(F, Ptab);
    const int idx = threadIdx.x;
    const int q2 = idx & (Q - 1);
    const int q1 = idx >> 4;

    float2 acc[NIMG];
#pragma unroll
    for (int i = 0; i < NIMG; i++) acc[i] = make_float2(0.f, 0.f);
    const float invf2 = 1.0f / (float)(F * F);

    for (int r1 = 0; r1 < F; r1++) {
        const int k1 = q1 + Q * r1;
        const float2 p1 = Ptab[k1];
        for (int r2 = 0; r2 < F; r2++) {
            const int k2 = q2 + Q * r2;
            const size_t fidx = (size_t)k1 * MM + k2;
            const float s = (fidx < lp_cap) ? lp[fidx] : 0.0f;
            if (s == 0.0f) continue;
            float2 pf = cmul(p1, Ptab[k2]);
            const float m = s * invf2;
            const float2 wv = make_float2(m * pf.x, m * pf.y);
#pragma unroll
            for (int img = 0; img < NIMG; img++) {
                float2 xv = g_X[(size_t)img * (MM * MM) + fidx];
                acc[img].x += xv.x * wv.x - xv.y * wv.y;
                acc[img].y += xv.x * wv.y + xv.y * wv.x;
            }
        }
    }
#pragma unroll
    for (int img = 0; img < NIMG; img++) {
        size_t o = w_off + (size_t)img * (Q * Q) + q1 * Q + q2;
        if (o < POOL_CAP) g_P[o] = acc[img];
    }
}

// ============================================================================
// Merged launches
// ============================================================================
// A: blocks [0,384): hp pass1 (g_X -> FT); [384,1749): folds
__global__ void __launch_bounds__(256) kernelA(
    const float* __restrict__ hp, size_t hs,
    const float* __restrict__ ang, size_t as_,
    const float* __restrict__ sc, size_t ss,
    const float* __restrict__ lp, size_t ls) {
    extern __shared__ unsigned char dyn[];
    __shared__ float2 Ptab[MM];
    const int b = blockIdx.x;
    const size_t scj = 262144u;
    if (b < 384) {
        sfft_body<16, 2, false, false>(b & 31, b >> 5, (float2*)dyn,
            nullptr, 0, 0, 0, nullptr, 0, 0, 1, OFF_FT, hp, hs, +1, 1.0f);
    } else {
        int fb = b - 384;
        if (fb < 1024)
            fold_body(2, 256, fb, ang, as_, sc, ss, OFF_W0, Ptab);
        else if (fb < 1280)
            fold_body(4, 128, fb - 1024, ang, as_, sc + scj, ss > scj ? ss - scj : 0, OFF_W1, Ptab);
        else if (fb < 1344)
            fold_body(8, 64, fb - 1280, ang, as_, sc + 2 * scj, ss > 2 * scj ? ss - 2 * scj : 0, OFF_W2, Ptab);
        else if (fb < 1360)
            fold_body(16, 32, fb - 1344, ang, as_, sc + 3 * scj, ss > 3 * scj ? ss - 3 * scj : 0, OFF_W3, Ptab);
        else if (fb < 1364)
            fold_body(32, 16, fb - 1360, ang, as_, sc + 4 * scj, ss > 4 * scj ? ss - 4 * scj : 0, OFF_W4, Ptab);
        else
            fold_low_body(lp, ls, OFF_WL, Ptab);
    }
}

// B: [0,384) hp pass2 -> out0; [384,768) j0 pass1; [768,1152) j1 pass1;
//    [1152,1308) fused small bands -> out3..6
__global__ void __launch_bounds__(256) kernelB(float* __restrict__ outf, size_t capf) {
    extern __shared__ unsigned char dyn[];
    __shared__ float2 twbuf[64];
    __shared__ int invbuf[64];
    const int b = blockIdx.x;
    if (b < 384) {
        sfft_body<16, 2, false, true>(b & 31, b >> 5, (float2*)dyn,
            nullptr, 0, 1, OFF_FT, outf, 0, capf, 0, 0, nullptr, 0, +1, 1.0f / 262144.0f);
    } else if (b < 768) {
        int bb = b - 384;
        sfft_body<8, 4, false, false>(bb & 7, bb >> 3, (float2*)dyn,
            nullptr, 0, 1, OFF_W0, nullptr, 0, 0, 1, OFF_T0, nullptr, 0, +1, 1.0f);
    } else if (b < 1152) {
        int bb = b - 768;
        sfft_body<4, 2, false, false>(bb & 7, bb >> 3, (float2*)dyn,
            nullptr, 0, 1, OFF_W1, nullptr, 0, 0, 1, OFF_T1, nullptr, 0, +1, 1.0f);
    } else {
        int fb = b - 1152;
        if (fb < 48)
            fused_body<64>(dyn, twbuf, invbuf, OFF_W2, fb, outf, 7077888, capf, 1.0f / 4096.0f);
        else if (fb < 96)
            fused_body<32>(dyn, twbuf, invbuf, OFF_W3, fb - 48, outf, 7274496, capf, 1.0f / 1024.0f);
        else if (fb < 144)
            fused_body<16>(dyn, twbuf, invbuf, OFF_W4, fb - 96, outf, 7323648, capf, 1.0f / 256.0f);
        else
            fused_body<16>(dyn, twbuf, invbuf, OFF_WL, fb - 144, outf, 7335936, capf, 1.0f / 256.0f);
    }
}

// C: [0,384) j0 pass2 -> out1; [384,768) j1 pass2 -> out2
__global__ void __launch_bounds__(256) kernelC(float* __restrict__ outf, size_t capf) {
    extern __shared__ unsigned char dyn[];
    const int b = blockIdx.x;
    if (b < 384) {
        sfft_body<8, 4, false, true>(b & 7, b >> 3, (float2*)dyn,
            nullptr, 0, 1, OFF_T0, outf, 3145728, capf, 0, 0, nullptr, 0, +1, 1.0f / 65536.0f);
    } else {
        int bb = b - 384;
        sfft_body<4, 2, false, true>(bb & 7, bb >> 3, (float2*)dyn,
            nullptr, 0, 1, OFF_T1, outf, 6291456, capf, 0, 0, nullptr, 0, +1, 1.0f / 16384.0f);
    }
}

// ---------------------------------------------------------------------------
typedef int (*cuGetRange_t)(unsigned long long*, size_t*, unsigned long long);
static size_t dout_capacity_f(void* d_out, int out_size) {
    size_t bytes = 0;
    void* h = dlopen("libcuda.so.1", RTLD_NOW | RTLD_GLOBAL);
    if (!h) h = dlopen("libcuda.so", RTLD_NOW | RTLD_GLOBAL);
    if (h) {
        cuGetRange_t f = (cuGetRange_t)dlsym(h, "cuMemGetAddressRange_v2");
        if (!f) f = (cuGetRange_t)dlsym(h, "cuMemGetAddressRange");
        if (f) {
            unsigned long long base = 0; size_t sz = 0;
            if (f(&base, &sz, (unsigned long long)(uintptr_t)d_out) == 0 && sz > 0) {
                unsigned long long off = (unsigned long long)(uintptr_t)d_out - base;
                if (off < sz) bytes = sz - off;
            }
        }
    }
    if (bytes == 0) bytes = (size_t)out_size * 4u;
    size_t cap = bytes / 4u;
    if (cap > OUT_TOTAL) cap = OUT_TOTAL;
    return cap;
}

extern "C" void kernel_launch(void* const* d_in, const int* in_sizes, int n_in,
                              void* d_out, int out_size) {
    const float *x = nullptr, *hp = nullptr, *lp = nullptr, *ang = nullptr, *sc = nullptr;
    size_t xs = 0, hs = 0, ls = 0, as_ = 0, ss = 0;
    for (int i = 0; i < n_in; i++) {
        size_t s = (size_t)in_sizes[i];
        const float* p = (const float*)d_in[i];
        if (s == 3145728u && !x)        { x = p;  xs = s; }
        else if (s == 1048576u && !ang) { ang = p; as_ = s; }
        else if (s == 1310720u && !sc)  { sc = p; ss = s; }
        else if (s == 262144u) { if (!hp) { hp = p; hs = s; } else if (!lp) { lp = p; ls = s; } }
    }
    if (!x  && n_in > 0) { x  = (const float*)d_in[0]; xs  = (size_t)in_sizes[0]; }
    if (!hp && n_in > 1) { hp = (const float*)d_in[1]; hs  = (size_t)in_sizes[1]; }
    if (!lp && n_in > 2) { lp = (const float*)d_in[2]; ls  = (size_t)in_sizes[2]; }
    if (!ang&& n_in > 3) { ang= (const float*)d_in[3]; as_ = (size_t)in_sizes[3]; }
    if (!sc && n_in > 4) { sc = (const float*)d_in[4]; ss  = (size_t)in_sizes[4]; }

    float* outf = (float*)d_out;
    const size_t capf = dout_capacity_f(d_out, out_size);

    // dynamic smem: sfft L=512 needs (8*513+16)*8 = 32960 B
    const int smL512 = (8 * 513 + 16) * 8;           // 32960
    const int smB    = 2 * 64 * (64 + PADR) * 8;     // 67584 (fused Q=64 dominates B)
    const int smC    = (8 * 257 + 8) * 8;            // 16512

    cudaFuncSetAttribute(kernelB, cudaFuncAttributeMaxDynamicSharedMemorySize, smB);

    const dim3 blk(256);

    // 1-2) forward FFT2 of x -> g_X
    sfft_kernel<16, 2, true , false><<<dim3(32, NIMG), blk, smL512>>>(
        x, xs, 0, 0, nullptr, 0, 0, 1, OFF_FT, nullptr, 0, -1, 1.0f);
    sfft_kernel<16, 2, false, false><<<dim3(32, NIMG), blk, smL512>>>(
        nullptr, 0, 1, OFF_FT, nullptr, 0, 0, 0, 0, nullptr, 0, -1, 1.0f);

    // 3) A: hp pass1 || all folds
    kernelA<<<1749, blk, smL512>>>(hp, hs, ang, as_, sc, ss, lp, ls);

    // 4) B: hp pass2 || j0 pass1 || j1 pass1 || fused small bands
    kernelB<<<1308, blk, smB>>>(outf, capf);

    // 5) C: j0 pass2 || j1 pass2
    kernelC<<<768, blk, smC>>>(outf, capf);
}